// round 16
// baseline (speedup 1.0000x reference)
#include <cuda_runtime.h>
#include <cuda_fp16.h>
#include <math.h>
#include <stdint.h>

#define B_  16
#define C_  768
#define N_  4096
#define BN_ 65536
#define M_  1024

#define KC      64                   // K halves per pipeline chunk (4 x k16 mma)
#define STAGES  3
#define STAGE_BYTES (128 * 128)      // 128 rows x 64 halves, swizzled, no pad
#define DYN_SMEM (STAGES * 2 * STAGE_BYTES)   // 98304 B -> 2 CTAs/SM
#define NT_GEMM 128                  // threads per GEMM CTA (4 warps, 2x2)
#define PREP_SMEM (32 * 769 * 4)     // 98432 B

// scratch (allocation-free __device__ globals)
__device__ __half g_zh[(size_t)BN_ * C_];     // half(z * rz), K-major [bn][c]
__device__ __half g_memh[M_ * C_];            // half(mem * rm)        [m][c]
__device__ __half g_memTh[C_ * M_];           // half(mem) transposed  [c][m]
__device__ __half g_exph[(size_t)BN_ * M_];   // half exp(score)       [bn][m]
__device__ float  g_psum[(size_t)BN_ * 8];    // per-row partial sums (8 m-blocks)
__device__ float  g_rsum[BN_];                // 1 / sum_m exp(score)

// ---------------------------------------------------------------- helpers ---
__device__ __forceinline__ uint32_t smem_u32(const void* p) {
    uint32_t a;
    asm("{ .reg .u64 t; cvta.to.shared.u64 t, %1; cvt.u32.u64 %0, t; }"
        : "=r"(a) : "l"(p));
    return a;
}
__device__ __forceinline__ void cp16(uint32_t dst, const void* src) {
    asm volatile("cp.async.cg.shared.global [%0], [%1], 16;" :: "r"(dst), "l"(src));
}
__device__ __forceinline__ void cp_commit() {
    asm volatile("cp.async.commit_group;\n" ::: "memory");
}
template <int W>
__device__ __forceinline__ void cp_wait() {
    asm volatile("cp.async.wait_group %0;\n" :: "n"(W) : "memory");
}
__device__ __forceinline__ void mma16(float* d, const uint32_t* a, const uint32_t* b) {
    asm volatile(
        "mma.sync.aligned.m16n8k16.row.col.f32.f16.f16.f32 "
        "{%0,%1,%2,%3}, {%4,%5,%6,%7}, {%8,%9}, {%0,%1,%2,%3};\n"
        : "+f"(d[0]), "+f"(d[1]), "+f"(d[2]), "+f"(d[3])
        : "r"(a[0]), "r"(a[1]), "r"(a[2]), "r"(a[3]), "r"(b[0]), "r"(b[1]));
}
__device__ __forceinline__ void ldm_x4(uint32_t* r, uint32_t addr) {
    asm volatile("ldmatrix.sync.aligned.m8n8.x4.shared.b16 {%0,%1,%2,%3}, [%4];"
                 : "=r"(r[0]), "=r"(r[1]), "=r"(r[2]), "=r"(r[3]) : "r"(addr));
}
// swizzled physical byte offset: row r (stride 128B), 16B chunk c -> c ^ (r&7)
__device__ __forceinline__ uint32_t swz(int r, int c) {
    return (uint32_t)(r * 128) + (uint32_t)((c ^ (r & 7)) << 4);
}

// stage loader (128 threads): 128 rows x KC halves for A and B
__device__ __forceinline__ void load_tile(uint32_t dstA, uint32_t dstB,
                                          const __half* srcA, const __half* srcB,
                                          int tid, int ldA, int ldB) {
#pragma unroll
    for (int q = 0; q < 8; ++q) {
        int e = q * NT_GEMM + tid;
        int r = e >> 3, kq = e & 7;
        cp16(dstA + swz(r, kq), srcA + (size_t)r * ldA + kq * 8);
    }
#pragma unroll
    for (int q = 0; q < 8; ++q) {
        int e = q * NT_GEMM + tid;
        int r = e >> 3, kq = e & 7;
        cp16(dstB + swz(r, kq), srcB + (size_t)r * ldB + kq * 8);
    }
}

// ------------------------------------------------------------- GEMM core ----
// D[128 x 128] = A[128 x K] * B[128 x K]^T, fp16 in, fp32 acc.
// 4 warps as 2x2; warp tile 64x64; 3-stage cp.async pipeline; ldmatrix frags;
// single barrier per iteration.
__device__ __forceinline__ void gemm_main(char* sm_, int T_,
                                          const __half* Asrc, const __half* Bsrc,
                                          int ldA, int ldB, int tid,
                                          int wm, int wn, int lane,
                                          float acc[4][8][4]) {
#pragma unroll
    for (int i = 0; i < 4; ++i)
#pragma unroll
        for (int j = 0; j < 8; ++j)
#pragma unroll
            for (int q = 0; q < 4; ++q) acc[i][j][q] = 0.f;

    uint32_t Asm = smem_u32(sm_);
    uint32_t Bsm = Asm + STAGES * STAGE_BYTES;

    const int l7 = lane & 7, lg = lane >> 3;          // lg: 0..3
    int rowA[4], rowB[4];
#pragma unroll
    for (int mt = 0; mt < 4; ++mt) rowA[mt] = wm * 64 + mt * 16 + (lg & 1) * 8 + l7;
#pragma unroll
    for (int p = 0; p < 4; ++p)    rowB[p] = wn * 64 + p * 16 + (lg >> 1) * 8 + l7;
    const int cA = lg >> 1;                            // A chunk offset
    const int cB = lg & 1;                             // B chunk offset

    load_tile(Asm, Bsm, Asrc, Bsrc, tid, ldA, ldB);
    cp_commit();
    load_tile(Asm + STAGE_BYTES, Bsm + STAGE_BYTES, Asrc + KC, Bsrc + KC,
              tid, ldA, ldB);
    cp_commit();

    for (int it = 0; it < T_; ++it) {
        cp_wait<1>();
        __syncthreads();   // single barrier/iter; guards data + stage reuse
        if (it + 2 < T_) {
            int s = (it + 2) % STAGES;
            load_tile(Asm + s * STAGE_BYTES, Bsm + s * STAGE_BYTES,
                      Asrc + (size_t)(it + 2) * KC, Bsrc + (size_t)(it + 2) * KC,
                      tid, ldA, ldB);
        }
        cp_commit();
        uint32_t Ab = Asm + (it % STAGES) * STAGE_BYTES;
        uint32_t Bb = Bsm + (it % STAGES) * STAGE_BYTES;
#pragma unroll
        for (int kk = 0; kk < KC; kk += 16) {
            const int ck = kk >> 3;
            uint32_t af[4][4], bf[8][2];
#pragma unroll
            for (int mt = 0; mt < 4; ++mt)
                ldm_x4(af[mt], Ab + swz(rowA[mt], ck + cA));
#pragma unroll
            for (int p = 0; p < 4; ++p) {
                uint32_t t[4];
                ldm_x4(t, Bb + swz(rowB[p], ck + cB));
                bf[2 * p][0] = t[0];
                bf[2 * p][1] = t[1];
                bf[2 * p + 1][0] = t[2];
                bf[2 * p + 1][1] = t[3];
            }
#pragma unroll
            for (int mt = 0; mt < 4; ++mt)
#pragma unroll
                for (int nt = 0; nt < 8; ++nt) mma16(acc[mt][nt], af[mt], bf[nt]);
        }
    }
}

// ---------------------------------------------------------------- prep ------
// One kernel: rm + memh + memTh. 32 blocks, each owns 32 memory rows.
__global__ void __launch_bounds__(256) k_prep_all(const float* __restrict__ mem) {
    extern __shared__ float tile[];   // [32][769]
    __shared__ float rm_s[32];
    const int tid = threadIdx.x;
    const int m0 = blockIdx.x * 32;

    for (int rr = 0; rr < 32; ++rr)
        for (int c = tid; c < C_; c += 256)
            tile[rr * 769 + c] = mem[(size_t)(m0 + rr) * C_ + c];
    __syncthreads();

    {
        int r = tid >> 3, sub = tid & 7;
        float s = 0.f;
        for (int c = sub; c < C_; c += 8) {
            float v = tile[r * 769 + c];
            s = fmaf(v, v, s);
        }
        s += __shfl_xor_sync(0xffffffffu, s, 1);
        s += __shfl_xor_sync(0xffffffffu, s, 2);
        s += __shfl_xor_sync(0xffffffffu, s, 4);
        if (sub == 0) rm_s[r] = 1.0f / fmaxf(sqrtf(s), 1e-12f);
    }
    __syncthreads();

    for (int rr = 0; rr < 32; ++rr) {
        float rm = rm_s[rr];
        for (int c = tid; c < C_; c += 256)
            g_memh[(size_t)(m0 + rr) * C_ + c] =
                __float2half_rn(tile[rr * 769 + c] * rm);
    }
    for (int e = tid; e < C_ * 32; e += 256) {
        int j = e & 31, c = e >> 5;
        g_memTh[(size_t)c * M_ + m0 + j] = __float2half_rn(tile[j * 769 + c]);
    }
}

// zh[bn][c] = half(z[b,c,n] * rz[bn])  — fused transpose + L2 norm.
__global__ void __launch_bounds__(256, 2) k_zt_h(const float* __restrict__ z) {
    __shared__ float tile[C_ * 17];   // [768][17] pad
    __shared__ float part[16][17];
    __shared__ float rzv[16];
    int blk = blockIdx.x;
    int b = blk >> 8;                 // 256 blocks per batch (4096/16)
    int n0 = (blk & 255) << 4;
    const float* zb = z + (size_t)b * (C_ * N_) + n0;
    int tid = threadIdx.x;
#pragma unroll 4
    for (int e = tid; e < C_ * 16; e += 256) {
        int c = e >> 4, nl = e & 15;
        tile[c * 17 + nl] = zb[(size_t)c * N_ + nl];
    }
    __syncthreads();
    {
        int col = tid & 15, j = tid >> 4;   // 16 threads per column
        float acc = 0.f;
#pragma unroll
        for (int c = j; c < C_; c += 16) {
            float v = tile[c * 17 + col];
            acc = fmaf(v, v, acc);
        }
        part[j][col] = acc;
    }
    __syncthreads();
    if (tid < 16) {
        float s = 0.f;
#pragma unroll
        for (int j = 0; j < 16; ++j) s += part[j][tid];
        rzv[tid] = 1.0f / fmaxf(sqrtf(s), 1e-12f);
    }
    __syncthreads();
    __half* out = g_zh + (size_t)(b * N_ + n0) * C_;
#pragma unroll 4
    for (int e = tid; e < C_ * 16; e += 256) {
        int nl = e / C_;
        int c = e - nl * C_;
        out[(size_t)nl * C_ + c] = __float2half_rn(tile[c * 17 + nl] * rzv[nl]);
    }
}

// ---------------------------------------------------------------- GEMM1 -----
// g_exph[row][m] = half(exp(score)); also emits per-row partial sums of exp
// over this CTA's 128 m-cols into g_psum[row][blockIdx.x].
__global__ void __launch_bounds__(NT_GEMM, 2) k_gemm1_h() {
    extern __shared__ __align__(128) char sm_[];
    __shared__ float sp[2][128];
    const int tid = threadIdx.x, lane = tid & 31, warp = tid >> 5;
    const int g = lane >> 2, tg = lane & 3;
    const int wm = warp >> 1, wn = warp & 1;
    const int m0 = blockIdx.x * 128;
    const int row0 = blockIdx.y * 128;

    float acc[4][8][4];
    gemm_main(sm_, C_ / KC, g_zh + (size_t)row0 * C_, g_memh + (size_t)m0 * C_,
              C_, C_, tid, wm, wn, lane, acc);

    float s_lo[4], s_hi[4];
#pragma unroll
    for (int mt = 0; mt < 4; ++mt) { s_lo[mt] = 0.f; s_hi[mt] = 0.f; }
#pragma unroll
    for (int mt = 0; mt < 4; ++mt) {
        int r = row0 + wm * 64 + mt * 16 + g;
#pragma unroll
        for (int nt = 0; nt < 8; ++nt) {
            int col = m0 + wn * 64 + nt * 8 + 2 * tg;
            float e0 = __expf(acc[mt][nt][0]);
            float e1 = __expf(acc[mt][nt][1]);
            float e2 = __expf(acc[mt][nt][2]);
            float e3 = __expf(acc[mt][nt][3]);
            s_lo[mt] += e0 + e1;
            s_hi[mt] += e2 + e3;
            *(__half2*)(g_exph + (size_t)r * M_ + col)       = __floats2half2_rn(e0, e1);
            *(__half2*)(g_exph + (size_t)(r + 8) * M_ + col) = __floats2half2_rn(e2, e3);
        }
    }
#pragma unroll
    for (int mt = 0; mt < 4; ++mt) {
        float a = s_lo[mt], bb = s_hi[mt];
        a += __shfl_xor_sync(0xffffffffu, a, 1);
        a += __shfl_xor_sync(0xffffffffu, a, 2);
        bb += __shfl_xor_sync(0xffffffffu, bb, 1);
        bb += __shfl_xor_sync(0xffffffffu, bb, 2);
        if (tg == 0) {
            sp[wn][wm * 64 + mt * 16 + g]     = a;
            sp[wn][wm * 64 + mt * 16 + g + 8] = bb;
        }
    }
    __syncthreads();
    g_psum[(size_t)(row0 + tid) * 8 + blockIdx.x] = sp[0][tid] + sp[1][tid];
}

// ---------------------------------------------------------------- rsum ------
__global__ void k_rsum() {
    int row = blockIdx.x * 256 + threadIdx.x;
    const float* p = g_psum + (size_t)row * 8;
    float s = 0.f;
#pragma unroll
    for (int i = 0; i < 8; ++i) s += p[i];
    g_rsum[row] = 1.0f / s;
}

// ---------------------------------------------------------------- GEMM2 -----
// zhat[b,c,n] = rsum[row] * sum_m exph[row][m] * memTh[c][m]
// Each CTA also writes the float attn rows r === blockIdx.x (mod 6) of its
// row-block — work spread evenly over the 6 c-CTAs per row-block.
__global__ void __launch_bounds__(NT_GEMM, 2) k_gemm2_h(float* __restrict__ zhat,
                                                        float* __restrict__ attn) {
    extern __shared__ __align__(128) char sm_[];
    const int tid = threadIdx.x, lane = tid & 31, warp = tid >> 5;
    const int g = lane >> 2, tg = lane & 3;
    const int wm = warp >> 1, wn = warp & 1;
    const int c0 = blockIdx.x * 128;
    const int row0 = blockIdx.y * 128;

    float acc[4][8][4];
    gemm_main(sm_, M_ / KC, g_exph + (size_t)row0 * M_, g_memTh + (size_t)c0 * M_,
              M_, M_, tid, wm, wn, lane, acc);

    __syncthreads();   // mainloop smem reads done; reuse as transpose staging
    float* smf = (float*)sm_;          // [128 cols][132] = 67584 B < 96 KB
#pragma unroll
    for (int mt = 0; mt < 4; ++mt) {
        int r = wm * 64 + mt * 16 + g;
        float rs0 = g_rsum[row0 + r];
        float rs1 = g_rsum[row0 + r + 8];
#pragma unroll
        for (int nt = 0; nt < 8; ++nt) {
            int col = wn * 64 + nt * 8 + 2 * tg;
            smf[(size_t)col * 132 + r]           = acc[mt][nt][0] * rs0;
            smf[(size_t)(col + 1) * 132 + r]     = acc[mt][nt][1] * rs0;
            smf[(size_t)col * 132 + r + 8]       = acc[mt][nt][2] * rs1;
            smf[(size_t)(col + 1) * 132 + r + 8] = acc[mt][nt][3] * rs1;
        }
    }
    __syncthreads();

    const int b = row0 >> 12;
    const int n0 = row0 & (N_ - 1);
    float* base = zhat + (size_t)b * (C_ * N_) + n0;
#pragma unroll
    for (int p = 0; p < 32; ++p) {
        int e = p * NT_GEMM + tid;
        int cc = e >> 5, q4 = e & 31;
        float4 v = *(const float4*)(smf + (size_t)cc * 132 + q4 * 4);
        *(float4*)(base + (size_t)(c0 + cc) * N_ + q4 * 4) = v;
    }

    // attn output: rows r === blockIdx.x (mod 6), ~21 rows per CTA (L2-warm)
    {
        const __half* ex = g_exph + (size_t)row0 * M_;
        for (int r = blockIdx.x; r < 128; r += C_ / 128) {
            float rs = g_rsum[row0 + r];
            uint4 u = *(const uint4*)(ex + (size_t)r * M_ + tid * 8);
            __half2 h0 = *(__half2*)&u.x, h1 = *(__half2*)&u.y;
            __half2 h2 = *(__half2*)&u.z, h3 = *(__half2*)&u.w;
            float2 f0 = __half22float2(h0), f1 = __half22float2(h1);
            float2 f2 = __half22float2(h2), f3 = __half22float2(h3);
            float4 o0, o1;
            o0.x = f0.x * rs; o0.y = f0.y * rs; o0.z = f1.x * rs; o0.w = f1.y * rs;
            o1.x = f2.x * rs; o1.y = f2.y * rs; o1.z = f3.x * rs; o1.w = f3.y * rs;
            float* arow = attn + (size_t)(row0 + r) * M_ + tid * 8;
            *(float4*)(arow)     = o0;
            *(float4*)(arow + 4) = o1;
        }
    }
}

// ---------------------------------------------------------------------------
extern "C" void kernel_launch(void* const* d_in, const int* in_sizes, int n_in,
                              void* d_out, int out_size) {
    const float* z   = (const float*)d_in[0];
    const float* mem = (const float*)d_in[1];
    float* zhat = (float*)d_out;
    float* attn = zhat + (size_t)B_ * C_ * N_;

    cudaFuncSetAttribute(k_prep_all, cudaFuncAttributeMaxDynamicSharedMemorySize, PREP_SMEM);
    cudaFuncSetAttribute(k_gemm1_h, cudaFuncAttributeMaxDynamicSharedMemorySize, DYN_SMEM);
    cudaFuncSetAttribute(k_gemm2_h, cudaFuncAttributeMaxDynamicSharedMemorySize, DYN_SMEM);

    k_prep_all<<<32, 256, PREP_SMEM>>>(mem);
    k_zt_h<<<BN_ / 16, 256>>>(z);
    k_gemm1_h<<<dim3(M_ / 128, BN_ / 128), NT_GEMM, DYN_SMEM>>>();
    k_rsum<<<BN_ / 256, 256>>>();
    k_gemm2_h<<<dim3(C_ / 128, BN_ / 128), NT_GEMM, DYN_SMEM>>>(zhat, attn);
}

// round 17
// speedup vs baseline: 1.0631x; 1.0631x over previous
#include <cuda_runtime.h>
#include <cuda_fp16.h>
#include <math.h>
#include <stdint.h>

#define B_  16
#define C_  768
#define N_  4096
#define BN_ 65536
#define M_  1024

#define KC      64                   // K halves per pipeline chunk (4 x k16 mma)
#define STAGES  3
#define STAGE_BYTES (128 * 128)      // 128 rows x 64 halves, swizzled, no pad
#define DYN_SMEM (STAGES * 2 * STAGE_BYTES)   // 98304 B -> 2 CTAs/SM
#define NT_GEMM 128                  // threads per GEMM CTA (4 warps, 2x2)

// scratch (allocation-free __device__ globals)
__device__ __half g_zh[(size_t)BN_ * C_];     // half(z * rz), K-major [bn][c]
__device__ __half g_memh[M_ * C_];            // half(mem * rm)        [m][c]
__device__ __half g_memTh[C_ * M_];           // half(mem) transposed  [c][m]
__device__ __half g_exph[(size_t)BN_ * M_];   // half exp(score)       [bn][m]
__device__ float  g_psum[(size_t)BN_ * 8];    // per-row partial sums (8 m-blocks)
__device__ float  g_rm[M_];

// ---------------------------------------------------------------- helpers ---
__device__ __forceinline__ uint32_t smem_u32(const void* p) {
    uint32_t a;
    asm("{ .reg .u64 t; cvta.to.shared.u64 t, %1; cvt.u32.u64 %0, t; }"
        : "=r"(a) : "l"(p));
    return a;
}
__device__ __forceinline__ void cp16(uint32_t dst, const void* src) {
    asm volatile("cp.async.cg.shared.global [%0], [%1], 16;" :: "r"(dst), "l"(src));
}
__device__ __forceinline__ void cp_commit() {
    asm volatile("cp.async.commit_group;\n" ::: "memory");
}
template <int W>
__device__ __forceinline__ void cp_wait() {
    asm volatile("cp.async.wait_group %0;\n" :: "n"(W) : "memory");
}
__device__ __forceinline__ void mma16(float* d, const uint32_t* a, const uint32_t* b) {
    asm volatile(
        "mma.sync.aligned.m16n8k16.row.col.f32.f16.f16.f32 "
        "{%0,%1,%2,%3}, {%4,%5,%6,%7}, {%8,%9}, {%0,%1,%2,%3};\n"
        : "+f"(d[0]), "+f"(d[1]), "+f"(d[2]), "+f"(d[3])
        : "r"(a[0]), "r"(a[1]), "r"(a[2]), "r"(a[3]), "r"(b[0]), "r"(b[1]));
}
__device__ __forceinline__ void ldm_x4(uint32_t* r, uint32_t addr) {
    asm volatile("ldmatrix.sync.aligned.m8n8.x4.shared.b16 {%0,%1,%2,%3}, [%4];"
                 : "=r"(r[0]), "=r"(r[1]), "=r"(r[2]), "=r"(r[3]) : "r"(addr));
}
// swizzled physical byte offset: row r (stride 128B), 16B chunk c -> c ^ (r&7)
__device__ __forceinline__ uint32_t swz(int r, int c) {
    return (uint32_t)(r * 128) + (uint32_t)((c ^ (r & 7)) << 4);
}

// stage loader (128 threads): 128 rows x KC halves for A and B
__device__ __forceinline__ void load_tile(uint32_t dstA, uint32_t dstB,
                                          const __half* srcA, const __half* srcB,
                                          int tid, int ldA, int ldB) {
#pragma unroll
    for (int q = 0; q < 8; ++q) {
        int e = q * NT_GEMM + tid;
        int r = e >> 3, kq = e & 7;
        cp16(dstA + swz(r, kq), srcA + (size_t)r * ldA + kq * 8);
    }
#pragma unroll
    for (int q = 0; q < 8; ++q) {
        int e = q * NT_GEMM + tid;
        int r = e >> 3, kq = e & 7;
        cp16(dstB + swz(r, kq), srcB + (size_t)r * ldB + kq * 8);
    }
}

// ------------------------------------------------------------- GEMM core ----
// D[128 x 128] = A[128 x K] * B[128 x K]^T, fp16 in, fp32 acc.
// 4 warps as 2x2; warp tile 64x64; 3-stage cp.async pipeline; ldmatrix frags;
// single barrier per iteration.
__device__ __forceinline__ void gemm_main(char* sm_, int T_,
                                          const __half* Asrc, const __half* Bsrc,
                                          int ldA, int ldB, int tid,
                                          int wm, int wn, int lane,
                                          float acc[4][8][4]) {
#pragma unroll
    for (int i = 0; i < 4; ++i)
#pragma unroll
        for (int j = 0; j < 8; ++j)
#pragma unroll
            for (int q = 0; q < 4; ++q) acc[i][j][q] = 0.f;

    uint32_t Asm = smem_u32(sm_);
    uint32_t Bsm = Asm + STAGES * STAGE_BYTES;

    const int l7 = lane & 7, lg = lane >> 3;          // lg: 0..3
    int rowA[4], rowB[4];
#pragma unroll
    for (int mt = 0; mt < 4; ++mt) rowA[mt] = wm * 64 + mt * 16 + (lg & 1) * 8 + l7;
#pragma unroll
    for (int p = 0; p < 4; ++p)    rowB[p] = wn * 64 + p * 16 + (lg >> 1) * 8 + l7;
    const int cA = lg >> 1;                            // A chunk offset
    const int cB = lg & 1;                             // B chunk offset

    load_tile(Asm, Bsm, Asrc, Bsrc, tid, ldA, ldB);
    cp_commit();
    load_tile(Asm + STAGE_BYTES, Bsm + STAGE_BYTES, Asrc + KC, Bsrc + KC,
              tid, ldA, ldB);
    cp_commit();

    for (int it = 0; it < T_; ++it) {
        cp_wait<1>();
        __syncthreads();   // single barrier/iter; guards data + stage reuse
        if (it + 2 < T_) {
            int s = (it + 2) % STAGES;
            load_tile(Asm + s * STAGE_BYTES, Bsm + s * STAGE_BYTES,
                      Asrc + (size_t)(it + 2) * KC, Bsrc + (size_t)(it + 2) * KC,
                      tid, ldA, ldB);
        }
        cp_commit();
        uint32_t Ab = Asm + (it % STAGES) * STAGE_BYTES;
        uint32_t Bb = Bsm + (it % STAGES) * STAGE_BYTES;
#pragma unroll
        for (int kk = 0; kk < KC; kk += 16) {
            const int ck = kk >> 3;
            uint32_t af[4][4], bf[8][2];
#pragma unroll
            for (int mt = 0; mt < 4; ++mt)
                ldm_x4(af[mt], Ab + swz(rowA[mt], ck + cA));
#pragma unroll
            for (int p = 0; p < 4; ++p) {
                uint32_t t[4];
                ldm_x4(t, Bb + swz(rowB[p], ck + cB));
                bf[2 * p][0] = t[0];
                bf[2 * p][1] = t[1];
                bf[2 * p + 1][0] = t[2];
                bf[2 * p + 1][1] = t[3];
            }
#pragma unroll
            for (int mt = 0; mt < 4; ++mt)
#pragma unroll
                for (int nt = 0; nt < 8; ++nt) mma16(acc[mt][nt], af[mt], bf[nt]);
        }
    }
}

// ---------------------------------------------------------------- prep ------
__global__ void k_rnorm_m(const float* __restrict__ mem) {
    int m = blockIdx.x;
    const float* p = mem + m * C_;
    float acc = 0.f;
    for (int c = threadIdx.x; c < C_; c += 128) {
        float v = p[c];
        acc = fmaf(v, v, acc);
    }
#pragma unroll
    for (int o = 16; o; o >>= 1) acc += __shfl_xor_sync(0xffffffffu, acc, o);
    __shared__ float s[4];
    if ((threadIdx.x & 31) == 0) s[threadIdx.x >> 5] = acc;
    __syncthreads();
    if (threadIdx.x == 0)
        g_rm[m] = 1.0f / fmaxf(sqrtf(s[0] + s[1] + s[2] + s[3]), 1e-12f);
}

__global__ void k_prep(const float* __restrict__ mem) {
    __shared__ float t[32][33];
    int c0 = blockIdx.x << 5, m0 = blockIdx.y << 5;
    int tx = threadIdx.x, ty = threadIdx.y;
    float v = mem[(size_t)(m0 + ty) * C_ + c0 + tx];
    g_memh[(size_t)(m0 + ty) * C_ + c0 + tx] = __float2half_rn(v * g_rm[m0 + ty]);
    t[ty][tx] = v;
    __syncthreads();
    g_memTh[(size_t)(c0 + ty) * M_ + m0 + tx] = __float2half_rn(t[tx][ty]);
}

// zh[bn][c] = half(z[b,c,n] * rz[bn])  — fused transpose + L2 norm.
__global__ void __launch_bounds__(256, 2) k_zt_h(const float* __restrict__ z) {
    __shared__ float tile[C_ * 17];   // [768][17] pad
    __shared__ float part[16][17];
    __shared__ float rzv[16];
    int blk = blockIdx.x;
    int b = blk >> 8;                 // 256 blocks per batch (4096/16)
    int n0 = (blk & 255) << 4;
    const float* zb = z + (size_t)b * (C_ * N_) + n0;
    int tid = threadIdx.x;
#pragma unroll 4
    for (int e = tid; e < C_ * 16; e += 256) {
        int c = e >> 4, nl = e & 15;
        tile[c * 17 + nl] = zb[(size_t)c * N_ + nl];
    }
    __syncthreads();
    {
        int col = tid & 15, j = tid >> 4;   // 16 threads per column
        float acc = 0.f;
#pragma unroll
        for (int c = j; c < C_; c += 16) {
            float v = tile[c * 17 + col];
            acc = fmaf(v, v, acc);
        }
        part[j][col] = acc;
    }
    __syncthreads();
    if (tid < 16) {
        float s = 0.f;
#pragma unroll
        for (int j = 0; j < 16; ++j) s += part[j][tid];
        rzv[tid] = 1.0f / fmaxf(sqrtf(s), 1e-12f);
    }
    __syncthreads();
    __half* out = g_zh + (size_t)(b * N_ + n0) * C_;
#pragma unroll 4
    for (int e = tid; e < C_ * 16; e += 256) {
        int nl = e / C_;
        int c = e - nl * C_;
        out[(size_t)nl * C_ + c] = __float2half_rn(tile[c * 17 + nl] * rzv[nl]);
    }
}

// ---------------------------------------------------------------- GEMM1 -----
// g_exph[row][m] = half(exp(score)); also emits per-row partial sums of exp
// over this CTA's 128 m-cols into g_psum[row][blockIdx.x].
__global__ void __launch_bounds__(NT_GEMM, 2) k_gemm1_h() {
    extern __shared__ __align__(128) char sm_[];
    __shared__ float sp[2][128];
    const int tid = threadIdx.x, lane = tid & 31, warp = tid >> 5;
    const int g = lane >> 2, tg = lane & 3;
    const int wm = warp >> 1, wn = warp & 1;
    const int m0 = blockIdx.x * 128;
    const int row0 = blockIdx.y * 128;

    float acc[4][8][4];
    gemm_main(sm_, C_ / KC, g_zh + (size_t)row0 * C_, g_memh + (size_t)m0 * C_,
              C_, C_, tid, wm, wn, lane, acc);

    float s_lo[4], s_hi[4];
#pragma unroll
    for (int mt = 0; mt < 4; ++mt) { s_lo[mt] = 0.f; s_hi[mt] = 0.f; }
#pragma unroll
    for (int mt = 0; mt < 4; ++mt) {
        int r = row0 + wm * 64 + mt * 16 + g;
#pragma unroll
        for (int nt = 0; nt < 8; ++nt) {
            int col = m0 + wn * 64 + nt * 8 + 2 * tg;
            float e0 = __expf(acc[mt][nt][0]);
            float e1 = __expf(acc[mt][nt][1]);
            float e2 = __expf(acc[mt][nt][2]);
            float e3 = __expf(acc[mt][nt][3]);
            s_lo[mt] += e0 + e1;
            s_hi[mt] += e2 + e3;
            *(__half2*)(g_exph + (size_t)r * M_ + col)       = __floats2half2_rn(e0, e1);
            *(__half2*)(g_exph + (size_t)(r + 8) * M_ + col) = __floats2half2_rn(e2, e3);
        }
    }
#pragma unroll
    for (int mt = 0; mt < 4; ++mt) {
        float a = s_lo[mt], bb = s_hi[mt];
        a += __shfl_xor_sync(0xffffffffu, a, 1);
        a += __shfl_xor_sync(0xffffffffu, a, 2);
        bb += __shfl_xor_sync(0xffffffffu, bb, 1);
        bb += __shfl_xor_sync(0xffffffffu, bb, 2);
        if (tg == 0) {
            sp[wn][wm * 64 + mt * 16 + g]     = a;
            sp[wn][wm * 64 + mt * 16 + g + 8] = bb;
        }
    }
    __syncthreads();
    g_psum[(size_t)(row0 + tid) * 8 + blockIdx.x] = sp[0][tid] + sp[1][tid];
}

// ---------------------------------------------------------------- GEMM2 -----
// zhat[b,c,n] = rsum[row] * sum_m exph[row][m] * memTh[c][m]
// rsum folded in: psum loads issued BEFORE the mainloop (latency hidden behind
// the GEMM), summed after. Each CTA also writes the float attn rows
// r === blockIdx.x (mod 6) of its row-block.
__global__ void __launch_bounds__(NT_GEMM, 2) k_gemm2_h(float* __restrict__ zhat,
                                                        float* __restrict__ attn) {
    extern __shared__ __align__(128) char sm_[];
    __shared__ float rsum_s[128];
    const int tid = threadIdx.x, lane = tid & 31, warp = tid >> 5;
    const int g = lane >> 2, tg = lane & 3;
    const int wm = warp >> 1, wn = warp & 1;
    const int c0 = blockIdx.x * 128;
    const int row0 = blockIdx.y * 128;

    // issue psum loads now; consumed only after the mainloop
    float4 ps0 = __ldg((const float4*)(g_psum + (size_t)(row0 + tid) * 8));
    float4 ps1 = __ldg((const float4*)(g_psum + (size_t)(row0 + tid) * 8 + 4));

    float acc[4][8][4];
    gemm_main(sm_, M_ / KC, g_exph + (size_t)row0 * M_, g_memTh + (size_t)c0 * M_,
              M_, M_, tid, wm, wn, lane, acc);

    rsum_s[tid] = 1.0f / (ps0.x + ps0.y + ps0.z + ps0.w +
                          ps1.x + ps1.y + ps1.z + ps1.w);
    __syncthreads();   // mainloop smem reads done + rsum_s visible
    float* smf = (float*)sm_;          // [128 cols][132] = 67584 B < 96 KB
#pragma unroll
    for (int mt = 0; mt < 4; ++mt) {
        int r = wm * 64 + mt * 16 + g;
        float rs0 = rsum_s[r];
        float rs1 = rsum_s[r + 8];
#pragma unroll
        for (int nt = 0; nt < 8; ++nt) {
            int col = wn * 64 + nt * 8 + 2 * tg;
            smf[(size_t)col * 132 + r]           = acc[mt][nt][0] * rs0;
            smf[(size_t)(col + 1) * 132 + r]     = acc[mt][nt][1] * rs0;
            smf[(size_t)col * 132 + r + 8]       = acc[mt][nt][2] * rs1;
            smf[(size_t)(col + 1) * 132 + r + 8] = acc[mt][nt][3] * rs1;
        }
    }
    __syncthreads();

    const int b = row0 >> 12;
    const int n0 = row0 & (N_ - 1);
    float* base = zhat + (size_t)b * (C_ * N_) + n0;
#pragma unroll
    for (int p = 0; p < 32; ++p) {
        int e = p * NT_GEMM + tid;
        int cc = e >> 5, q4 = e & 31;
        float4 v = *(const float4*)(smf + (size_t)cc * 132 + q4 * 4);
        *(float4*)(base + (size_t)(c0 + cc) * N_ + q4 * 4) = v;
    }

    // attn output: rows r === blockIdx.x (mod 6), ~21 rows per CTA (L2-warm)
    {
        const __half* ex = g_exph + (size_t)row0 * M_;
        for (int r = blockIdx.x; r < 128; r += C_ / 128) {
            float rs = rsum_s[r];
            uint4 u = *(const uint4*)(ex + (size_t)r * M_ + tid * 8);
            __half2 h0 = *(__half2*)&u.x, h1 = *(__half2*)&u.y;
            __half2 h2 = *(__half2*)&u.z, h3 = *(__half2*)&u.w;
            float2 f0 = __half22float2(h0), f1 = __half22float2(h1);
            float2 f2 = __half22float2(h2), f3 = __half22float2(h3);
            float4 o0, o1;
            o0.x = f0.x * rs; o0.y = f0.y * rs; o0.z = f1.x * rs; o0.w = f1.y * rs;
            o1.x = f2.x * rs; o1.y = f2.y * rs; o1.z = f3.x * rs; o1.w = f3.y * rs;
            float* arow = attn + (size_t)(row0 + r) * M_ + tid * 8;
            *(float4*)(arow)     = o0;
            *(float4*)(arow + 4) = o1;
        }
    }
}

// ---------------------------------------------------------------------------
extern "C" void kernel_launch(void* const* d_in, const int* in_sizes, int n_in,
                              void* d_out, int out_size) {
    const float* z   = (const float*)d_in[0];
    const float* mem = (const float*)d_in[1];
    float* zhat = (float*)d_out;
    float* attn = zhat + (size_t)B_ * C_ * N_;

    cudaFuncSetAttribute(k_gemm1_h, cudaFuncAttributeMaxDynamicSharedMemorySize, DYN_SMEM);
    cudaFuncSetAttribute(k_gemm2_h, cudaFuncAttributeMaxDynamicSharedMemorySize, DYN_SMEM);

    k_rnorm_m<<<M_, 128>>>(mem);
    k_prep<<<dim3(C_ / 32, M_ / 32), dim3(32, 32)>>>(mem);
    k_zt_h<<<BN_ / 16, 256>>>(z);
    k_gemm1_h<<<dim3(M_ / 128, BN_ / 128), NT_GEMM, DYN_SMEM>>>();
    k_gemm2_h<<<dim3(C_ / 128, BN_ / 128), NT_GEMM, DYN_SMEM>>>(zhat, attn);
}